// round 1
// baseline (speedup 1.0000x reference)
#include <cuda_runtime.h>
#include <math.h>
#include <stdint.h>

#define A_N 49104
#define B_N 8
#define C_N 80
#define K_N 256
#define IMG 512.0f
#define EQCAP 2048

// -------- device scratch (no allocations allowed) --------
__device__ float  g_scores[B_N * A_N];
__device__ int    g_labels[B_N * A_N];
__device__ float4 g_boxes [B_N * A_N];
__device__ float4 g_topb  [B_N * K_N];
__device__ float  g_tops  [B_N * K_N];
__device__ int    g_topl  [B_N * K_N];

// ============================================================
// Stage A: per-anchor class max/argmax + sigmoid + box decode
// ============================================================
__global__ void stageA(const float* __restrict__ cls,
                       const float* __restrict__ regs,
                       const float* __restrict__ anchors) {
    int idx = blockIdx.x * blockDim.x + threadIdx.x;
    if (idx >= B_N * A_N) return;

    const float4* p = reinterpret_cast<const float4*>(cls) + (size_t)idx * (C_N / 4);
    float m = -INFINITY;
    int arg = 0;
#pragma unroll
    for (int i = 0; i < C_N / 4; i++) {
        float4 v = p[i];
        int c = i * 4;
        if (v.x > m) { m = v.x; arg = c; }
        if (v.y > m) { m = v.y; arg = c + 1; }
        if (v.z > m) { m = v.z; arg = c + 2; }
        if (v.w > m) { m = v.w; arg = c + 3; }
    }
    float score = 1.0f / (1.0f + expf(-m));
    if (!(score > 0.01f)) score = 0.0f;

    int a = idx % A_N;
    float4 an = reinterpret_cast<const float4*>(anchors)[a];
    float aw = an.z - an.x;
    float ah = an.w - an.y;
    float acx = an.x + 0.5f * aw;
    float acy = an.y + 0.5f * ah;
    float4 rg = reinterpret_cast<const float4*>(regs)[idx];
    float cx = acx + rg.x * aw;
    float cy = acy + rg.y * ah;
    float dw = fminf(fmaxf(rg.z, -4.0f), 4.0f);
    float dh = fminf(fmaxf(rg.w, -4.0f), 4.0f);
    float w = aw * expf(dw);
    float h = ah * expf(dh);
    float x1 = fminf(fmaxf(cx - 0.5f * w, 0.0f), IMG);
    float y1 = fminf(fmaxf(cy - 0.5f * h, 0.0f), IMG);
    float x2 = fminf(fmaxf(cx + 0.5f * w, 0.0f), IMG);
    float y2 = fminf(fmaxf(cy + 0.5f * h, 0.0f), IMG);

    g_scores[idx] = score;
    g_labels[idx] = arg;
    g_boxes[idx]  = make_float4(x1, y1, x2, y2);
}

// ============================================================
// Stage B: exact top-256 per batch (lax.top_k semantics)
//   radix-select on float bit-pattern (all scores >= 0),
//   then bitonic sort 256 by (score desc, index asc).
// ============================================================
__global__ __launch_bounds__(1024) void stageB() {
    int b = blockIdx.x;
    const float* s = g_scores + b * A_N;
    int tid = threadIdx.x;

    __shared__ unsigned hist[256];
    __shared__ unsigned sh_prefix, sh_remaining;
    __shared__ unsigned long long top[K_N];
    __shared__ unsigned eqbuf[EQCAP];
    __shared__ unsigned gt_cnt, eq_cnt;

    if (tid == 0) { sh_prefix = 0u; sh_remaining = K_N; }
    __syncthreads();

    // 4x 8-bit MSB-first radix select
    for (int p = 0; p < 4; p++) {
        int shift = 24 - 8 * p;
        for (int i = tid; i < 256; i += blockDim.x) hist[i] = 0;
        __syncthreads();
        unsigned prefix = sh_prefix;
        unsigned himask = (p == 0) ? 0u : (0xFFFFFFFFu << (shift + 8));
        for (int a = tid; a < A_N; a += blockDim.x) {
            unsigned k = __float_as_uint(s[a]);
            if ((k & himask) == prefix)
                atomicAdd(&hist[(k >> shift) & 255u], 1u);
        }
        __syncthreads();
        if (tid == 0) {
            unsigned rem = sh_remaining;
            unsigned cum = 0;
            int bin = 0;
            for (int bb = 255; bb >= 0; bb--) {
                if (cum + hist[bb] >= rem) { bin = bb; break; }
                cum += hist[bb];
            }
            sh_prefix = prefix | ((unsigned)bin << shift);
            sh_remaining = rem - cum;
        }
        __syncthreads();
    }

    unsigned T = sh_prefix;
    unsigned need_eq = sh_remaining;  // #entries equal to T to take (lowest index first)
    if (tid == 0) { gt_cnt = 0; eq_cnt = 0; }
    __syncthreads();

    // collect strictly-greater and equal candidates
    for (int a = tid; a < A_N; a += blockDim.x) {
        unsigned k = __float_as_uint(s[a]);
        if (k > T) {
            unsigned pz = atomicAdd(&gt_cnt, 1u);
            top[pz] = (((unsigned long long)k) << 32) | (unsigned)(0xFFFFFFFFu - (unsigned)a);
        } else if (k == T) {
            unsigned pz = atomicAdd(&eq_cnt, 1u);
            if (pz < EQCAP) eqbuf[pz] = (unsigned)a;
        }
    }
    __syncthreads();
    unsigned G = gt_cnt;

    // sort equal-key indices ascending (bitonic over pow2 size)
    unsigned ec = min(eq_cnt, (unsigned)EQCAP);
    unsigned n = 1;
    while (n < ec) n <<= 1;
    if (n < 2) n = 2;
    for (unsigned i = tid; i < n; i += blockDim.x)
        if (i >= ec) eqbuf[i] = 0xFFFFFFFFu;
    __syncthreads();
    for (unsigned kk = 2; kk <= n; kk <<= 1) {
        for (unsigned j = kk >> 1; j > 0; j >>= 1) {
            for (unsigned t = tid; t < n; t += blockDim.x) {
                unsigned ixj = t ^ j;
                if (ixj > t) {
                    unsigned x = eqbuf[t], y = eqbuf[ixj];
                    bool asc = ((t & kk) == 0);
                    bool doswap = asc ? (x > y) : (x < y);
                    if (doswap) { eqbuf[t] = y; eqbuf[ixj] = x; }
                }
            }
            __syncthreads();
        }
    }
    // append the needed equal-key entries
    for (unsigned t = tid; t < need_eq && G + t < K_N; t += blockDim.x)
        top[G + t] = (((unsigned long long)T) << 32) | (unsigned)(0xFFFFFFFFu - eqbuf[t]);
    __syncthreads();

    // bitonic sort 256 entries descending (key: score bits hi, ~index lo)
    for (unsigned kk = 2; kk <= K_N; kk <<= 1) {
        for (unsigned j = kk >> 1; j > 0; j >>= 1) {
            for (unsigned t = tid; t < K_N; t += blockDim.x) {
                unsigned ixj = t ^ j;
                if (ixj > t) {
                    unsigned long long x = top[t], y = top[ixj];
                    bool descseg = ((t & kk) == 0);
                    bool doswap = descseg ? (x < y) : (x > y);
                    if (doswap) { top[t] = y; top[ixj] = x; }
                }
            }
            __syncthreads();
        }
    }

    // gather results
    for (unsigned t = tid; t < K_N; t += blockDim.x) {
        unsigned long long v = top[t];
        unsigned k = (unsigned)(v >> 32);
        unsigned a = 0xFFFFFFFFu - (unsigned)(v & 0xFFFFFFFFu);
        g_tops[b * K_N + t] = __uint_as_float(k);
        g_topl[b * K_N + t] = g_labels[b * A_N + a];
        g_topb[b * K_N + t] = g_boxes[b * A_N + a];
    }
}

// ============================================================
// Stage C: sequential NMS on 256 sorted candidates + output
// ============================================================
__global__ __launch_bounds__(K_N) void stageC(float* __restrict__ out, int out_size) {
    int b = blockIdx.x;
    int tid = threadIdx.x;

    __shared__ float4 bx[K_N];
    __shared__ float sc[K_N];
    __shared__ unsigned msk[K_N][8];
    __shared__ unsigned keepw[8];

    bx[tid] = g_topb[b * K_N + tid];
    sc[tid] = g_tops[b * K_N + tid];
    __syncthreads();

    float4 me = bx[tid];
    float myarea = fmaxf(me.z - me.x, 0.0f) * fmaxf(me.w - me.y, 0.0f);
    unsigned words[8] = {0u, 0u, 0u, 0u, 0u, 0u, 0u, 0u};
#pragma unroll 4
    for (int j = 0; j < K_N; j++) {
        float4 o = bx[j];
        float ix1 = fmaxf(me.x, o.x);
        float iy1 = fmaxf(me.y, o.y);
        float ix2 = fminf(me.z, o.z);
        float iy2 = fminf(me.w, o.w);
        float iw = fmaxf(ix2 - ix1, 0.0f);
        float ih = fmaxf(iy2 - iy1, 0.0f);
        float inter = iw * ih;
        float oarea = fmaxf(o.z - o.x, 0.0f) * fmaxf(o.w - o.y, 0.0f);
        float uni = myarea + oarea - inter;
        float iou = inter / fmaxf(uni, 1e-8f);
        if (iou > 0.5f) words[j >> 5] |= 1u << (j & 31);
    }
#pragma unroll
    for (int w = 0; w < 8; w++) msk[tid][w] = words[w];
    __syncthreads();

    if (tid == 0) {
#pragma unroll
        for (int w = 0; w < 8; w++) keepw[w] = 0u;
        for (int i = 0; i < K_N; i++) {
            bool k0 = sc[i] > 0.0f;
            unsigned sup = 0u;
            int wi = i >> 5;
            for (int w = 0; w < wi; w++) sup |= msk[i][w] & keepw[w];
            unsigned below = (1u << (i & 31)) - 1u;
            sup |= msk[i][wi] & keepw[wi] & below;
            if (k0 && sup == 0u) keepw[wi] |= 1u << (i & 31);
        }
    }
    __syncthreads();

    bool kp = (keepw[tid >> 5] >> (tid & 31)) & 1u;
    float kf = kp ? 1.0f : 0.0f;
    int base = b * K_N + tid;

    // dets [B,K,5]
    out[base * 5 + 0] = me.x * kf;
    out[base * 5 + 1] = me.y * kf;
    out[base * 5 + 2] = me.z * kf;
    out[base * 5 + 3] = me.w * kf;
    out[base * 5 + 4] = sc[tid] * kf;
    // labels [B,K] (as float), keep [B,K] (as float), guarded by out_size
    if (out_size >= B_N * K_N * 5 + B_N * K_N)
        out[B_N * K_N * 5 + base] = (float)g_topl[base];
    if (out_size >= B_N * K_N * 5 + 2 * B_N * K_N)
        out[B_N * K_N * 5 + B_N * K_N + base] = kf;
}

// ============================================================
extern "C" void kernel_launch(void* const* d_in, const int* in_sizes, int n_in,
                              void* d_out, int out_size) {
    // Identify inputs by element count (robust to ordering):
    //   cls_logits: 8*49104*80 = 31426560
    //   box_regs:   8*49104*4  =  1571328
    //   anchors:    49104*4    =   196416
    const float* cls = nullptr;
    const float* regs = nullptr;
    const float* anchors = nullptr;
    for (int i = 0; i < n_in; i++) {
        if (in_sizes[i] == B_N * A_N * C_N) cls = (const float*)d_in[i];
        else if (in_sizes[i] == B_N * A_N * 4) regs = (const float*)d_in[i];
        else if (in_sizes[i] == A_N * 4) anchors = (const float*)d_in[i];
    }
    if (!cls || !regs || !anchors) return;

    float* out = (float*)d_out;

    int total = B_N * A_N;
    stageA<<<(total + 255) / 256, 256>>>(cls, regs, anchors);
    stageB<<<B_N, 1024>>>();
    stageC<<<B_N, K_N>>>(out, out_size);
}